// round 7
// baseline (speedup 1.0000x reference)
#include <cuda_runtime.h>
#include <math.h>

#define HEIGHT 1024
#define WIDTH  2048
#define PPT 4      // pixels per thread (4 | 2048, float4 aligned)
#define TPB 256

// Grid trig tables, filled each call by init kernel (deterministic).
__device__ float g_sth[HEIGHT];
__device__ float g_cth[HEIGHT];
__device__ float g_sph[WIDTH];
__device__ float g_cph[WIDTH];

// Replicate the reference grid EXACTLY at float32 granularity:
//   theta = fl32( fl32(gx * fl32(pi/2)) + fl32(pi/2) ),  gx = -1 + 2i/1024 (exact)
//   phi   = fl32( gy * fl32(pi) ),                       gy = -1 + j/1024 (exact)
// then sin/cos evaluated in double and rounded -> within <=1 ulp of numpy float32.
__global__ void init_tables_kernel()
{
    const int i = blockIdx.x * blockDim.x + threadIdx.x;
    if (i < HEIGHT) {
        const float gx = -1.0f + (float)i * (2.0f / (float)HEIGHT); // exact
        const float th = __fadd_rn(__fmul_rn(gx, 1.5707963267948966f),
                                   1.5707963267948966f);
        const double td = (double)th;
        g_sth[i] = (float)sin(td);
        g_cth[i] = (float)cos(td);
    }
    if (i < WIDTH) {
        const float gy = -1.0f + (float)i * (2.0f / (float)WIDTH);  // exact
        const float ph = __fmul_rn(gy, 3.14159265358979323846f);
        const double pd = (double)ph;
        g_sph[i] = (float)sin(pd);
        g_cph[i] = (float)cos(pd);
    }
}

__global__ void __launch_bounds__(TPB)
depth3dgrid_kernel(const float* __restrict__ depth,
                   const float* __restrict__ trans,
                   float* __restrict__ out)
{
    __shared__ float sT[16];
    const int b = blockIdx.y;
    if (threadIdx.x < 16) sT[threadIdx.x] = trans[b * 16 + threadIdx.x];
    __syncthreads();

    // 4 consecutive pixels, same row
    const int base = (blockIdx.x * TPB + threadIdx.x) * PPT;
    const int h  = base >> 11;          // / WIDTH
    const int w0 = base & (WIDTH - 1);  // % WIDTH

    const float T00 = sT[0],  T01 = sT[1],  T02 = sT[2];
    const float T10 = sT[4],  T11 = sT[5],  T12 = sT[6];
    const float T20 = sT[8],  T21 = sT[9],  T22 = sT[10];
    const float T30 = sT[12], T31 = sT[13], T32 = sT[14];

    const float s_th = g_sth[h];
    const float c_th = g_cth[h];

    const float4 cpv = *(const float4*)&g_cph[w0];
    const float4 spv = *(const float4*)&g_sph[w0];
    const float4 dv  = *(const float4*)(depth + (size_t)b * (HEIGHT * WIDTH) + base);

    const float cpa[4] = {cpv.x, cpv.y, cpv.z, cpv.w};
    const float spa[4] = {spv.x, spv.y, spv.z, spv.w};
    const float dd[4]  = {dv.x,  dv.y,  dv.z,  dv.w};

    float res[8];
#pragma unroll
    for (int k = 0; k < 4; ++k) {
        // grid point (matches ref: x = sin(th)*cos(ph), y = sin(th)*sin(ph), z = cos(th))
        const float x3 = __fmul_rn(s_th, cpa[k]);
        const float y3 = __fmul_rn(s_th, spa[k]);
        const float d  = dd[k];

        // xyz = grid * depth (same op as reference)
        const float xd = __fmul_rn(x3, d);
        const float yd = __fmul_rn(y3, d);
        const float zd = __fmul_rn(c_th, d);

        // p = [xd, yd, zd, 1] . T  (fma chains)
        const float px = fmaf(xd, T00, fmaf(yd, T10, fmaf(zd, T20, T30)));
        const float py = fmaf(xd, T01, fmaf(yd, T11, fmaf(zd, T21, T31)));
        const float pz = fmaf(xd, T02, fmaf(yd, T12, fmaf(zd, T22, T32)));

        // r = sqrt(px^2+py^2+pz^2) + 1e-4  (IEEE sqrt)
        const float s2 = fmaf(px, px, fmaf(py, py, __fmul_rn(pz, pz)));
        const float r  = __fadd_rn(__fsqrt_rn(s2), 1e-4f);
        const float t  = __fdiv_rn(pz, r);          // |t| < 1 guaranteed

        // theta = acos(t)/(pi/2) - 1 ; phi = atan2(py,px)/pi  (libm accuracy)
        const float theta_o = __fadd_rn(
            __fdiv_rn(acosf(t), 1.5707963267948966f), -1.0f);
        const float phi_o = __fdiv_rn(atan2f(py, px), 3.14159265358979323846f);

        res[2 * k]     = phi_o;    // channel 0 = phi
        res[2 * k + 1] = theta_o;  // channel 1 = theta
    }

    float4* optr = (float4*)(out + ((size_t)b * (HEIGHT * WIDTH) + base) * 2);
    optr[0] = make_float4(res[0], res[1], res[2], res[3]);
    optr[1] = make_float4(res[4], res[5], res[6], res[7]);
}

extern "C" void kernel_launch(void* const* d_in, const int* in_sizes, int n_in,
                              void* d_out, int out_size)
{
    const float* depth = (const float*)d_in[0];   // (4,1024,2048,1) f32
    const float* trans = (const float*)d_in[1];   // (4,4,4) f32
    float* out = (float*)d_out;                   // (4,1024,2048,2) f32

    init_tables_kernel<<<(WIDTH + 255) / 256, 256>>>();

    dim3 grid(HEIGHT * WIDTH / (TPB * PPT), 4, 1); // (2048, 4)
    depth3dgrid_kernel<<<grid, TPB>>>(depth, trans, out);
}

// round 8
// speedup vs baseline: 1.5333x; 1.5333x over previous
#include <cuda_runtime.h>
#include <math.h>

#define HEIGHT 1024
#define WIDTH  2048
#define PPT 4      // pixels per thread (4 | 2048, float4 aligned)
#define TPB 256

// Grid trig tables, filled each call by init kernel (deterministic).
__device__ float g_sth[HEIGHT];
__device__ float g_cth[HEIGHT];
__device__ float g_sph[WIDTH];
__device__ float g_cph[WIDTH];

// Replicate the reference grid EXACTLY at float32 granularity (same as the
// passing round-7 kernel -- this is what keeps atan2 branch-cut flips at zero):
//   theta = fl32( fl32(gx * fl32(pi/2)) + fl32(pi/2) ),  gx = -1 + 2i/1024 (exact)
//   phi   = fl32( gy * fl32(pi) ),                       gy = -1 + j/1024 (exact)
// sin/cos evaluated in double, rounded to float (<=1 ulp vs numpy float32).
// One sincos per thread for max parallelism on the FP64 path.
__global__ void init_tables_kernel()
{
    const int i = blockIdx.x * blockDim.x + threadIdx.x;
    if (i < HEIGHT) {
        const float gx = -1.0f + (float)i * (2.0f / (float)HEIGHT); // exact
        const float th = __fadd_rn(__fmul_rn(gx, 1.5707963267948966f),
                                   1.5707963267948966f);
        double s, c;
        sincos((double)th, &s, &c);
        g_sth[i] = (float)s;
        g_cth[i] = (float)c;
    } else if (i < HEIGHT + WIDTH) {
        const int j = i - HEIGHT;
        const float gy = -1.0f + (float)j * (2.0f / (float)WIDTH);  // exact
        const float ph = __fmul_rn(gy, 3.14159265358979323846f);
        double s, c;
        sincos((double)ph, &s, &c);
        g_sph[j] = (float)s;
        g_cph[j] = (float)c;
    }
}

__global__ void __launch_bounds__(TPB)
depth3dgrid_kernel(const float* __restrict__ depth,
                   const float* __restrict__ trans,
                   float* __restrict__ out)
{
    __shared__ float sT[16];
    const int b = blockIdx.y;
    if (threadIdx.x < 16) sT[threadIdx.x] = trans[b * 16 + threadIdx.x];
    __syncthreads();

    // 4 consecutive pixels, same row
    const int base = (blockIdx.x * TPB + threadIdx.x) * PPT;
    const int h  = base >> 11;          // / WIDTH
    const int w0 = base & (WIDTH - 1);  // % WIDTH

    const float T00 = sT[0],  T01 = sT[1],  T02 = sT[2];
    const float T10 = sT[4],  T11 = sT[5],  T12 = sT[6];
    const float T20 = sT[8],  T21 = sT[9],  T22 = sT[10];
    const float T30 = sT[12], T31 = sT[13], T32 = sT[14];

    const float s_th = g_sth[h];
    const float c_th = g_cth[h];

    const float4 cpv = *(const float4*)&g_cph[w0];
    const float4 spv = *(const float4*)&g_sph[w0];
    const float4 dv  = *(const float4*)(depth + (size_t)b * (HEIGHT * WIDTH) + base);

    const float cpa[4] = {cpv.x, cpv.y, cpv.z, cpv.w};
    const float spa[4] = {spv.x, spv.y, spv.z, spv.w};
    const float dd[4]  = {dv.x,  dv.y,  dv.z,  dv.w};

    const float PI     = 3.14159265358979323846f;
    const float HALFPI = 1.5707963267948966f;

    float res[8];
#pragma unroll
    for (int k = 0; k < 4; ++k) {
        // grid point * depth (bit-identical to the passing round-7 chain)
        const float x3 = __fmul_rn(s_th, cpa[k]);
        const float y3 = __fmul_rn(s_th, spa[k]);
        const float d  = dd[k];
        const float xd = __fmul_rn(x3, d);
        const float yd = __fmul_rn(y3, d);
        const float zd = __fmul_rn(c_th, d);

        // p = [xd, yd, zd, 1] . T  (same fma chain as round 7 -- sign-critical)
        const float px = fmaf(xd, T00, fmaf(yd, T10, fmaf(zd, T20, T30)));
        const float py = fmaf(xd, T01, fmaf(yd, T11, fmaf(zd, T21, T31)));
        const float pz = fmaf(xd, T02, fmaf(yd, T12, fmaf(zd, T22, T32)));

        // r = sqrt(s2) + 1e-4 via rsqrt;  t = pz / r  (|t| < 1 strictly)
        const float s2  = fmaxf(fmaf(px, px, fmaf(py, py, pz * pz)), 1e-30f);
        const float ris = rsqrtf(s2);
        const float r   = fmaf(s2, ris, 1e-4f);
        const float t   = __fdividef(pz, r);

        // acos(t) = sqrt(1-|t|) * P7(|t|)   (Hastings, abs err ~7e-8 rad)
        const float xa = fabsf(t);
        float p = fmaf(xa, -0.0012624911f, 0.0066700901f);
        p = fmaf(p, xa, -0.0170881256f);
        p = fmaf(p, xa,  0.0308918810f);
        p = fmaf(p, xa, -0.0501743046f);
        p = fmaf(p, xa,  0.0889789874f);
        p = fmaf(p, xa, -0.2145988016f);
        p = fmaf(p, xa,  1.5707963050f);
        const float u  = fmaxf(1.0f - xa, 1e-30f);
        float ac = p * (u * rsqrtf(u));              // p * sqrt(1-|t|)
        ac = (t >= 0.0f) ? ac : (PI - ac);
        const float theta_o = fmaf(ac, 0.6366197723675814f, -1.0f); // *2/pi - 1

        // atan2(py, px): degree-11 even minimax on [0,1] + quadrant fixes
        const float ax = fabsf(px), ay = fabsf(py);
        const float mx = fmaxf(fmaxf(ax, ay), 1e-37f);
        const float mn = fminf(ax, ay);
        const float a  = __fdividef(mn, mx);
        const float ss = a * a;
        float q = fmaf(ss, -0.0117212f, 0.0526533f);
        q = fmaf(q, ss, -0.1164329f);
        q = fmaf(q, ss,  0.1935435f);
        q = fmaf(q, ss, -0.3326235f);
        q = fmaf(q, ss,  0.9999773f);
        q = q * a;                                   // atan(mn/mx), [0, pi/4]
        q = (ay > ax)   ? (HALFPI - q) : q;
        q = (px < 0.0f) ? (PI - q)     : q;
        const float phi_o = copysignf(q, py) * 0.3183098861837907f; // /pi

        res[2 * k]     = phi_o;    // channel 0 = phi
        res[2 * k + 1] = theta_o;  // channel 1 = theta
    }

    float4* optr = (float4*)(out + ((size_t)b * (HEIGHT * WIDTH) + base) * 2);
    optr[0] = make_float4(res[0], res[1], res[2], res[3]);
    optr[1] = make_float4(res[4], res[5], res[6], res[7]);
}

extern "C" void kernel_launch(void* const* d_in, const int* in_sizes, int n_in,
                              void* d_out, int out_size)
{
    const float* depth = (const float*)d_in[0];   // (4,1024,2048,1) f32
    const float* trans = (const float*)d_in[1];   // (4,4,4) f32
    float* out = (float*)d_out;                   // (4,1024,2048,2) f32

    init_tables_kernel<<<(HEIGHT + WIDTH + 127) / 128, 128>>>();

    dim3 grid(HEIGHT * WIDTH / (TPB * PPT), 4, 1); // (2048, 4)
    depth3dgrid_kernel<<<grid, TPB>>>(depth, trans, out);
}

// round 9
// speedup vs baseline: 1.6779x; 1.0943x over previous
#include <cuda_runtime.h>
#include <math.h>

#define HEIGHT 1024
#define WIDTH  2048
#define PPT 4      // pixels per thread (4 | 2048, float4 aligned)
#define TPB 256

// Grid trig tables, filled each call by init kernel (deterministic).
__device__ float g_sth[HEIGHT];
__device__ float g_cth[HEIGHT];
__device__ float g_sph[WIDTH];
__device__ float g_cph[WIDTH];

// Replicate the reference grid EXACTLY at float32 granularity (unchanged from
// the passing round-7/8 kernels -- this keeps atan2 branch-cut flips at zero):
//   theta = fl32( fl32(gx * fl32(pi/2)) + fl32(pi/2) ),  gx = -1 + 2i/1024 (exact)
//   phi   = fl32( gy * fl32(pi) ),                       gy = -1 + j/1024 (exact)
// sin/cos evaluated in double, rounded to float (<=1 ulp vs numpy float32).
__global__ void init_tables_kernel()
{
    const int i = blockIdx.x * blockDim.x + threadIdx.x;
    if (i < HEIGHT) {
        const float gx = -1.0f + (float)i * (2.0f / (float)HEIGHT); // exact
        const float th = __fadd_rn(__fmul_rn(gx, 1.5707963267948966f),
                                   1.5707963267948966f);
        double s, c;
        sincos((double)th, &s, &c);
        g_sth[i] = (float)s;
        g_cth[i] = (float)c;
    } else if (i < HEIGHT + WIDTH) {
        const int j = i - HEIGHT;
        const float gy = -1.0f + (float)j * (2.0f / (float)WIDTH);  // exact
        const float ph = __fmul_rn(gy, 3.14159265358979323846f);
        double s, c;
        sincos((double)ph, &s, &c);
        g_sph[j] = (float)s;
        g_cph[j] = (float)c;
    }
}

__global__ void __launch_bounds__(TPB)
depth3dgrid_kernel(const float* __restrict__ depth,
                   const float* __restrict__ trans,
                   float* __restrict__ out)
{
    __shared__ float sT[16];
    const int b = blockIdx.y;
    if (threadIdx.x < 16) sT[threadIdx.x] = trans[b * 16 + threadIdx.x];
    __syncthreads();

    // 4 consecutive pixels, same row
    const int base = (blockIdx.x * TPB + threadIdx.x) * PPT;
    const int h  = base >> 11;          // / WIDTH
    const int w0 = base & (WIDTH - 1);  // % WIDTH

    const float s_th = g_sth[h];
    const float c_th = g_cth[h];

    // Row-constant hoist: p_j = d * (cp*(s_th*T0j) + sp*(s_th*T1j) + c_th*T2j) + T3j
    const float a0 = s_th * sT[0],  a1 = s_th * sT[1],  a2 = s_th * sT[2];
    const float b0 = s_th * sT[4],  b1 = s_th * sT[5],  b2 = s_th * sT[6];
    const float k0 = c_th * sT[8],  k1 = c_th * sT[9],  k2 = c_th * sT[10];
    const float T30 = sT[12], T31 = sT[13], T32 = sT[14];

    const float4 cpv = *(const float4*)&g_cph[w0];
    const float4 spv = *(const float4*)&g_sph[w0];
    const float4 dv  = *(const float4*)(depth + (size_t)b * (HEIGHT * WIDTH) + base);

    const float cpa[4] = {cpv.x, cpv.y, cpv.z, cpv.w};
    const float spa[4] = {spv.x, spv.y, spv.z, spv.w};
    const float dd[4]  = {dv.x,  dv.y,  dv.z,  dv.w};

    const float PI     = 3.14159265358979323846f;
    const float HALFPI = 1.5707963267948966f;

    float res[8];
#pragma unroll
    for (int k = 0; k < 4; ++k) {
        const float cp = cpa[k], sp = spa[k], d = dd[k];

        const float px = fmaf(d, fmaf(cp, a0, fmaf(sp, b0, k0)), T30);
        const float py = fmaf(d, fmaf(cp, a1, fmaf(sp, b1, k1)), T31);
        const float pz = fmaf(d, fmaf(cp, a2, fmaf(sp, b2, k2)), T32);

        // t = pz / (sqrt(s2) + 1e-4) via rsqrt + first-order expansion:
        // 1/(sqrt+eps) = ris*(1 - eps*ris) + O(eps^2), eps*ris ~ 1e-4
        const float s2  = fmaxf(fmaf(px, px, fmaf(py, py, pz * pz)), 1e-30f);
        const float ris = rsqrtf(s2);
        const float pr  = pz * ris;
        const float t   = fmaf(pr * ris, -1e-4f, pr);

        // acos(t) = sqrt(1-|t|) * P3(|t|)   (A&S 4.4.45, abs err <= 6.7e-5 rad)
        const float xa = fabsf(t);
        float p = fmaf(xa, -0.0187293f, 0.0742610f);
        p = fmaf(p, xa, -0.2121144f);
        p = fmaf(p, xa,  1.5707288f);
        const float u  = fmaxf(1.0f - xa, 1e-30f);
        float ac = p * (u * rsqrtf(u));              // p * sqrt(1-|t|)
        ac = (t >= 0.0f) ? ac : (PI - ac);
        const float theta_o = fmaf(ac, 0.6366197723675814f, -1.0f); // *2/pi - 1

        // atan2(py, px): degree-9 odd minimax on [0,1] + quadrant fixes
        const float ax = fabsf(px), ay = fabsf(py);
        const float mx = fmaxf(fmaxf(ax, ay), 1e-37f);
        const float mn = fminf(ax, ay);
        const float a  = __fdividef(mn, mx);
        const float ss = a * a;
        float q = fmaf(ss, 0.0208351f, -0.0851330f);
        q = fmaf(q, ss,  0.1801410f);
        q = fmaf(q, ss, -0.3302995f);
        q = fmaf(q, ss,  0.9998660f);
        q = q * a;                                   // atan(mn/mx), [0, pi/4]
        q = (ay > ax)   ? (HALFPI - q) : q;
        q = (px < 0.0f) ? (PI - q)     : q;
        const float phi_o = copysignf(q, py) * 0.3183098861837907f; // /pi

        res[2 * k]     = phi_o;    // channel 0 = phi
        res[2 * k + 1] = theta_o;  // channel 1 = theta
    }

    float4* optr = (float4*)(out + ((size_t)b * (HEIGHT * WIDTH) + base) * 2);
    optr[0] = make_float4(res[0], res[1], res[2], res[3]);
    optr[1] = make_float4(res[4], res[5], res[6], res[7]);
}

extern "C" void kernel_launch(void* const* d_in, const int* in_sizes, int n_in,
                              void* d_out, int out_size)
{
    const float* depth = (const float*)d_in[0];   // (4,1024,2048,1) f32
    const float* trans = (const float*)d_in[1];   // (4,4,4) f32
    float* out = (float*)d_out;                   // (4,1024,2048,2) f32

    init_tables_kernel<<<(HEIGHT + WIDTH + 127) / 128, 128>>>();

    dim3 grid(HEIGHT * WIDTH / (TPB * PPT), 4, 1); // (2048, 4)
    depth3dgrid_kernel<<<grid, TPB>>>(depth, trans, out);
}